// round 15
// baseline (speedup 1.0000x reference)
#include <cuda_runtime.h>
#include <math.h>

// ---------------- problem constants ----------------
#define BB     4
#define HISTN  24
#define PREDN  12
#define NNODE  10000
#define NEDGE  160000
#define TTOT   (HISTN + PREDN)   // 36
#define BN     (BB * NNODE)      // 40000
#define BE     (BB * NEDGE)      // 640000
#define FEATD  31
#define HIDN   64

// ---------------- persistent device scratch ----------------
__device__ __align__(16) float g_ps[(size_t)BN * 32];
__device__ __align__(16) float g_pt[(size_t)BN * 32];
__device__ float g_spd[BN];
__device__ float g_dir[BN];
__device__ __align__(16) float4 g_base4[8][NEDGE];     // transposed base planes
__device__ __align__(16) float g_agg[(size_t)BN * 12]; // 9 used + 3 pad
__device__ __align__(16) float g_h[(size_t)BN * 64];
__device__ float g_xn[BN];
__device__ float g_stats[4];     // mean0, mean1, rstd0, rstd1
__device__ double g_dsum[4];     // s0, s1, q0, q1 (restored to 0 by last k_gru)

// counting-sort state (g_cnt restored to 0 by last k_gru each launch)
__device__ int g_cnt[NNODE];
__device__ int4 g_erec[NEDGE];   // {es, et, dist_bits, cdir_bits} sorted by es

// HW tanh (sm_75+, 1 MUFU op)
__device__ __forceinline__ float htanh(float x) {
    float y;
    asm("tanh.approx.f32 %0, %1;" : "=f"(y) : "f"(x));
    return y;
}
__device__ __forceinline__ float sigf(float x) {
    return fmaf(0.5f, htanh(0.5f * x), 0.5f);
}

// packed fp32x2 FMA (Blackwell)
__device__ __forceinline__ float2 ffma2(float2 a, float2 b, float2 c) {
    float2 d;
    asm("fma.rn.f32x2 %0, %1, %2, %3;"
        : "=l"(*reinterpret_cast<unsigned long long*>(&d))
        : "l"(*reinterpret_cast<const unsigned long long*>(&a)),
          "l"(*reinterpret_cast<const unsigned long long*>(&b)),
          "l"(*reinterpret_cast<const unsigned long long*>(&c)));
    return d;
}

// vector reduction to global (no return) — sm_90+
__device__ __forceinline__ void red4(float* p, float a, float b, float c, float d) {
    asm volatile("red.global.add.v4.f32 [%0], {%1, %2, %3, %4};"
                 :: "l"(p), "f"(a), "f"(b), "f"(c), "f"(d) : "memory");
}

// ---------------- shared node-pre math ----------------
__device__ __forceinline__ void node_pre_math(
    int idx, float xn_v, const float* __restrict__ frow,
    const float* __restrict__ We1s,
    const float* __restrict__ wmean, const float* __restrict__ wstd)
{
    float x[32];
    x[0] = xn_v;
#pragma unroll
    for (int k = 0; k < FEATD; k++) x[1 + k] = frow[k];

    float2 a2[16];
#pragma unroll
    for (int q = 0; q < 16; q++) a2[q] = make_float2(0.f, 0.f);
#pragma unroll
    for (int k = 0; k < 32; k++) {
        float2 xd = make_float2(x[k], x[k]);
        const float4* w = (const float4*)&We1s[k * 32];
#pragma unroll
        for (int q = 0; q < 8; q++) {
            float4 wv = w[q];
            a2[2 * q]     = ffma2(make_float2(wv.x, wv.y), xd, a2[2 * q]);
            a2[2 * q + 1] = ffma2(make_float2(wv.z, wv.w), xd, a2[2 * q + 1]);
        }
    }
    float2* pso = (float2*)&g_ps[(size_t)idx * 32];
#pragma unroll
    for (int q = 0; q < 16; q++) pso[q] = a2[q];

#pragma unroll
    for (int q = 0; q < 16; q++) a2[q] = make_float2(0.f, 0.f);
#pragma unroll
    for (int k = 0; k < 32; k++) {
        float2 xd = make_float2(x[k], x[k]);
        const float4* w = (const float4*)&We1s[(32 + k) * 32];
#pragma unroll
        for (int q = 0; q < 8; q++) {
            float4 wv = w[q];
            a2[2 * q]     = ffma2(make_float2(wv.x, wv.y), xd, a2[2 * q]);
            a2[2 * q + 1] = ffma2(make_float2(wv.z, wv.w), xd, a2[2 * q + 1]);
        }
    }
    float2* pto = (float2*)&g_pt[(size_t)idx * 32];
#pragma unroll
    for (int q = 0; q < 16; q++) pto[q] = a2[q];

    g_spd[idx] = fmaf(x[30], wstd[0], wmean[0]);
    g_dir[idx] = fmaf(x[31], wstd[1], wmean[1]);

    float4 z4 = make_float4(0.f, 0.f, 0.f, 0.f);
    float4* ag = (float4*)&g_agg[(size_t)idx * 12];
    ag[0] = z4; ag[1] = z4; ag[2] = z4;
}

// ---------------- L1 (setup): histogram + stats partials ----------------
__global__ __launch_bounds__(256) void k_setup1(const int* __restrict__ eidx,
                                                const float* __restrict__ eattr) {
    __shared__ double sb[256];
    int tid = threadIdx.x;
    int e = blockIdx.x * 256 + tid;
    double a = 0.0, c = 0.0;
    if (e < NEDGE) {
        atomicAdd(&g_cnt[eidx[e]], 1);
        a = (double)eattr[2 * e];
        c = (double)eattr[2 * e + 1];
    }
    double vals[4] = { a, c, a * a, c * c };
#pragma unroll
    for (int v = 0; v < 4; v++) {
        sb[tid] = vals[v];
        __syncthreads();
        for (int off = 128; off > 0; off >>= 1) {
            if (tid < off) sb[tid] += sb[tid + off];
            __syncthreads();
        }
        if (tid == 0) atomicAdd(&g_dsum[v], sb[0]);
        __syncthreads();
    }
}

// ---------------- L2 (setup): finalize stats + exclusive scan ----------------
__global__ void k_scan() {
    __shared__ int s[1024];
    int tid = threadIdx.x;
    if (tid == 0) {
        double m0 = g_dsum[0] / NEDGE, m1 = g_dsum[1] / NEDGE;
        double v0 = (g_dsum[2] - (double)NEDGE * m0 * m0) / (double)(NEDGE - 1);
        double v1 = (g_dsum[3] - (double)NEDGE * m1 * m1) / (double)(NEDGE - 1);
        g_stats[0] = (float)m0;
        g_stats[1] = (float)m1;
        g_stats[2] = (float)(1.0 / sqrt(v0));
        g_stats[3] = (float)(1.0 / sqrt(v1));
    }
    int sum = 0;
    if (tid < 1000) {
#pragma unroll
        for (int j = 0; j < 10; j++) sum += g_cnt[tid * 10 + j];
    }
    s[tid] = sum;
    __syncthreads();
    for (int off = 1; off < 1024; off <<= 1) {
        int v = (tid >= off) ? s[tid - off] : 0;
        __syncthreads();
        s[tid] += v;
        __syncthreads();
    }
    if (tid < 1000) {
        int run = (tid > 0) ? s[tid - 1] : 0;
#pragma unroll
        for (int j = 0; j < 10; j++) {
            int c = g_cnt[tid * 10 + j];
            g_cnt[tid * 10 + j] = run;
            run += c;
        }
    }
}

// ---------------- L3 (setup): place edges + base planes + state init + node_pre(t=0) ----------------
__global__ __launch_bounds__(256) void k_place_pre(
    const int* __restrict__ eidx,
    const float* __restrict__ eattr,
    const float* __restrict__ We1,
    const float* __restrict__ be1,
    const float* __restrict__ rain,
    const float* __restrict__ feature,
    const float* __restrict__ wmean,
    const float* __restrict__ wstd)
{
    __shared__ __align__(16) float We1s[64 * 32];
    int tid = threadIdx.x;
    for (int i = tid; i < 64 * 32; i += 256) We1s[i] = We1[i];
    __syncthreads();

    int e = blockIdx.x * 256 + tid;

    if (e < BN) {
        int b = e / NNODE;
        int n = e - b * NNODE;
        float xn_v = rain[((size_t)b * HISTN + (HISTN - 1)) * NNODE + n];
        g_xn[e] = xn_v;
        float4 z = make_float4(0.f, 0.f, 0.f, 0.f);
        float4* hp = (float4*)&g_h[(size_t)e * 64];
#pragma unroll
        for (int q = 0; q < 16; q++) hp[q] = z;
        const float* frow = feature + ((size_t)(b * TTOT + HISTN + 0) * NNODE + n) * FEATD;
        node_pre_math(e, xn_v, frow, We1s, wmean, wstd);
    }

    if (e < NEDGE) {
        int es = eidx[e];
        int et = eidx[NEDGE + e];
        int pos = atomicAdd(&g_cnt[es], 1);
        float d = eattr[2 * e];
        float c = eattr[2 * e + 1];
        int4 rec;
        rec.x = es; rec.y = et;
        rec.z = __float_as_int(d);
        rec.w = __float_as_int(c);
        g_erec[pos] = rec;

        float m0 = g_stats[0], m1 = g_stats[1], r0 = g_stats[2], r1 = g_stats[3];
        float ean0 = (d - m0) * r0;
        float ean1 = (c - m1) * r1;
#pragma unroll
        for (int q = 0; q < 8; q++) {
            float4 v;
            v.x = fmaf(ean0, We1[64 * 32 + 4 * q + 0], fmaf(ean1, We1[65 * 32 + 4 * q + 0], be1[4 * q + 0]));
            v.y = fmaf(ean0, We1[64 * 32 + 4 * q + 1], fmaf(ean1, We1[65 * 32 + 4 * q + 1], be1[4 * q + 1]));
            v.z = fmaf(ean0, We1[64 * 32 + 4 * q + 2], fmaf(ean1, We1[65 * 32 + 4 * q + 2], be1[4 * q + 2]));
            v.w = fmaf(ean0, We1[64 * 32 + 4 * q + 3], fmaf(ean1, We1[65 * 32 + 4 * q + 3], be1[4 * q + 3]));
            g_base4[q][pos] = v;
        }
    }
}

// ---------------- per-step: per-node precompute (t >= 1) ----------------
__global__ __launch_bounds__(128) void k_node_pre(
    const float* __restrict__ feature,
    const float* __restrict__ We1,
    const float* __restrict__ wmean,
    const float* __restrict__ wstd,
    int t)
{
    __shared__ __align__(16) float We1s[64 * 32];
    int tid = threadIdx.x;
    for (int i = tid; i < 64 * 32; i += 128) We1s[i] = We1[i];
    __syncthreads();

    int idx = blockIdx.x * 128 + tid;
    if (idx >= BN) return;
    int b = idx / NNODE;
    int n = idx - b * NNODE;
    const float* frow = feature + ((size_t)(b * TTOT + HISTN + t) * NNODE + n) * FEATD;
    node_pre_math(idx, g_xn[idx], frow, We1s, wmean, wstd);
}

// ---------------- per-step: edge MLP + Wn projection + vector scatter-add ----------------
__global__ __launch_bounds__(256, 4) void k_edge(
    const float* __restrict__ We1,
    const float* __restrict__ We2,
    const float* __restrict__ be2,
    const float* __restrict__ Wn)
{
    __shared__ __align__(16) float We2sp[32 * 32];  // row stride 32, cols>=30 zero
    __shared__ __align__(16) float Wn_p[30 * 12];   // row stride 12, cols>=9 zero
    __shared__ __align__(16) float w66s[32];
    __shared__ __align__(16) float be2s[32];
    __shared__ float stage[8][32 * 33];             // per-warp pt tile, pad 33
    int tid = threadIdx.x;
    int wid = tid >> 5;
    int lane = tid & 31;

    for (int i = tid; i < 32 * 32; i += 256) We2sp[i] = 0.f;
    for (int i = tid; i < 30 * 12; i += 256) Wn_p[i] = 0.f;
    if (tid < 32) be2s[tid] = 0.f;
    __syncthreads();
    for (int i = tid; i < 32 * 30; i += 256) We2sp[(i / 30) * 32 + (i % 30)] = We2[i];
    for (int i = tid; i < 30 * 9; i += 256) Wn_p[(i / 9) * 12 + (i % 9)] = Wn[i];
    if (tid < 32) w66s[tid] = We1[66 * 32 + tid];
    if (tid < 30) be2s[tid] = be2[tid];
    __syncthreads();

    int gid = blockIdx.x * 256 + tid;       // BE == 2500*256 exactly, no tail
    int pos = gid >> 2;                     // 4 batches of same edge in same warp
    int b = gid & 3;

    int4 er = g_erec[pos];
    int es = er.x;
    int et = er.y;
    float dist = __int_as_float(er.z);
    float cdir = __int_as_float(er.w);
    int rs = b * NNODE + es;
    int rt = b * NNODE + et;

    // ---- cooperative pt stage: row per edge-slot, coalesced 128B line loads ----
    float* st = stage[wid];
#pragma unroll
    for (int r = 0; r < 32; r++) {
        int rowr = __shfl_sync(0xffffffffu, rt, r);
        st[r * 33 + lane] = g_pt[(size_t)rowr * 32 + lane];
    }
    __syncwarp();
    const float* myrow = st + lane * 33;    // conflict-free (stride 33)

    float spd = g_spd[rs];
    float dr = g_dir[rs];
    float theta = fabsf(cdir - dr);
    float ew = fmaxf(0.f, __fdividef(3.0f * spd * __cosf(theta * 22.5f), dist));

    const float4* p4 = (const float4*)&g_ps[(size_t)rs * 32];
    const float4* w4 = (const float4*)w66s;

    float h[32];
#pragma unroll
    for (int q = 0; q < 8; q++) {
        float4 a = p4[q], d = g_base4[q][pos], w = w4[q];
        h[4 * q + 0] = sigf(a.x + myrow[4 * q + 0] + d.x + ew * w.x);
        h[4 * q + 1] = sigf(a.y + myrow[4 * q + 1] + d.y + ew * w.y);
        h[4 * q + 2] = sigf(a.z + myrow[4 * q + 2] + d.z + ew * w.z);
        h[4 * q + 3] = sigf(a.w + myrow[4 * q + 3] + d.w + ew * w.w);
    }

    float2 a2[16];
#pragma unroll
    for (int q = 0; q < 16; q++) a2[q] = make_float2(be2s[2 * q], be2s[2 * q + 1]);
#pragma unroll 8
    for (int i = 0; i < 32; i++) {
        float2 hd = make_float2(h[i], h[i]);
        const float4* wv = (const float4*)&We2sp[i * 32];
#pragma unroll
        for (int q = 0; q < 8; q++) {
            float4 w = wv[q];
            a2[2 * q]     = ffma2(make_float2(w.x, w.y), hd, a2[2 * q]);
            a2[2 * q + 1] = ffma2(make_float2(w.z, w.w), hd, a2[2 * q + 1]);
        }
    }

    // sigmoid + project to 9 channels via Wn (padded to 12)
    float2 p2[6];
#pragma unroll
    for (int q = 0; q < 6; q++) p2[q] = make_float2(0.f, 0.f);
#pragma unroll
    for (int q = 0; q < 15; q++) {
        float e0 = sigf(a2[q].x);
        float e1 = sigf(a2[q].y);
        float2 e0d = make_float2(e0, e0);
        float2 e1d = make_float2(e1, e1);
        const float4* w0 = (const float4*)&Wn_p[(2 * q) * 12];
        const float4* w1 = (const float4*)&Wn_p[(2 * q + 1) * 12];
#pragma unroll
        for (int r = 0; r < 3; r++) {
            float4 wa = w0[r];
            float4 wb = w1[r];
            p2[2 * r]     = ffma2(make_float2(wa.x, wa.y), e0d, p2[2 * r]);
            p2[2 * r + 1] = ffma2(make_float2(wa.z, wa.w), e0d, p2[2 * r + 1]);
            p2[2 * r]     = ffma2(make_float2(wb.x, wb.y), e1d, p2[2 * r]);
            p2[2 * r + 1] = ffma2(make_float2(wb.z, wb.w), e1d, p2[2 * r + 1]);
        }
    }

    float v0 = p2[0].x, v1 = p2[0].y, v2 = p2[1].x, v3 = p2[1].y;
    float v4 = p2[2].x, v5 = p2[2].y, v6 = p2[3].x, v7 = p2[3].y;
    float v8 = p2[4].x;

    float* at  = &g_agg[(size_t)rt * 12];
    float* as_ = &g_agg[(size_t)rs * 12];
    red4(at, v0, v1, v2, v3);
    red4(at + 4, v4, v5, v6, v7);
    atomicAdd(at + 8, v8);
    red4(as_, -v0, -v1, -v2, -v3);
    red4(as_ + 4, -v4, -v5, -v6, -v7);
    atomicAdd(as_ + 8, -v8);
}

// ---------------- per-step: node GNN head + GRU + readout ----------------
#define GRU_WBUF_OFF 20624
#define GRU_SMEM_FLOATS (GRU_WBUF_OFF + 16 * 8 * 106 * 2)
#define GRU_SMEM_BYTES  (GRU_SMEM_FLOATS * 4)

__global__ __launch_bounds__(512) void k_gru(
    const float* __restrict__ bn_g,
    const float* __restrict__ Wih_g, const float* __restrict__ bih_g,
    const float* __restrict__ Whh_g, const float* __restrict__ bhh_g,
    const float* __restrict__ Wout_g, const float* __restrict__ bout_g,
    const float* __restrict__ feature,
    float* __restrict__ out, int t, int cleanup)
{
    extern __shared__ __align__(16) float sm[];
    float* Wih_s  = sm;
    float* Whh_s  = sm + 7872;
    float* bih_s  = sm + 20160;
    float* bhh_s  = sm + 20352;
    float* bn_s   = sm + 20544;
    float* Wout_s = sm + 20556;

    int tid = threadIdx.x;
    for (int i = tid; i < 7872; i += 512) Wih_s[i] = Wih_g[i];
    for (int i = tid; i < 12288; i += 512) Whh_s[i] = Whh_g[i];
    if (tid < 192) { bih_s[tid] = bih_g[tid]; bhh_s[tid] = bhh_g[tid]; }
    if (tid < 9) bn_s[tid] = bn_g[tid];
    if (tid < 64) Wout_s[tid] = Wout_g[tid];
    __syncthreads();

    int wid = tid >> 5;
    int lane = tid & 31;
    float2* wb = (float2*)(sm + GRU_WBUF_OFF) + wid * (8 * 106);

    float bout = bout_g[0];
    int u = lane * 2;

    int gw = blockIdx.x * 16 + wid;
    int nwarps = gridDim.x * 16;

    for (int g = gw; g < BN / 8; g += nwarps) {
        int base = g * 8;
        int b = base / NNODE;              // groups never straddle batches (8 | 10000)
        int nd0 = base - b * NNODE;
        const float* fbase = feature + ((size_t)(b * TTOT + HISTN + t) * NNODE + nd0) * FEATD;

#pragma unroll
        for (int n = 0; n < 8; n++) {
            int m = base + n;
            float2* xq = wb + n * 106;
            float2* hq = xq + 42;
            if (lane < 9) {
                float v = sigf(g_agg[(size_t)m * 12 + lane] + bn_s[lane]);
                xq[lane] = make_float2(v, v);
            } else if (lane == 9) {
                float xv = g_xn[m];
                xq[9] = make_float2(xv, xv);
            }
            if (lane < 31) {
                float f = fbase[(size_t)n * FEATD + lane];
                xq[10 + lane] = make_float2(f, f);
            }
            float h0 = g_h[(size_t)m * 64 + lane];
            float h1 = g_h[(size_t)m * 64 + 32 + lane];
            hq[lane] = make_float2(h0, h0);
            hq[32 + lane] = make_float2(h1, h1);
        }
        __syncwarp();

        float2 bi_r = *(const float2*)&bih_s[u];
        float2 bi_z = *(const float2*)&bih_s[u + 64];
        float2 bi_g = *(const float2*)&bih_s[u + 128];
        float2 bh_r = *(const float2*)&bhh_s[u];
        float2 bh_z = *(const float2*)&bhh_s[u + 64];
        float2 bh_g = *(const float2*)&bhh_s[u + 128];

        float2 ar[8], az[8], aig[8], ahg[8];
#pragma unroll
        for (int n = 0; n < 8; n++) {
            ar[n] = make_float2(bi_r.x + bh_r.x, bi_r.y + bh_r.y);
            az[n] = make_float2(bi_z.x + bh_z.x, bi_z.y + bh_z.y);
            aig[n] = bi_g;
            ahg[n] = bh_g;
        }

        const float2* row = (const float2*)Wih_s + lane;
#pragma unroll 2
        for (int k = 0; k < 41; k++) {
            float2 wr = row[0];
            float2 wz = row[32];
            float2 wg = row[64];
#pragma unroll
            for (int n = 0; n < 8; n++) {
                float2 xv = wb[n * 106 + k];
                ar[n]  = ffma2(wr, xv, ar[n]);
                az[n]  = ffma2(wz, xv, az[n]);
                aig[n] = ffma2(wg, xv, aig[n]);
            }
            row += 96;
        }

        const float2* rowh = (const float2*)Whh_s + lane;
#pragma unroll 2
        for (int k = 0; k < 64; k++) {
            float2 wr = rowh[0];
            float2 wz = rowh[32];
            float2 wg = rowh[64];
#pragma unroll
            for (int n = 0; n < 8; n++) {
                float2 hv = wb[n * 106 + 42 + k];
                ar[n]  = ffma2(wr, hv, ar[n]);
                az[n]  = ffma2(wz, hv, az[n]);
                ahg[n] = ffma2(wg, hv, ahg[n]);
            }
            rowh += 96;
        }

        float wo0 = Wout_s[u], wo1 = Wout_s[u + 1];

#pragma unroll
        for (int n = 0; n < 8; n++) {
            int m = base + n;
            const float2* hq = wb + n * 106 + 42;
            float hold0 = hq[u].x;
            float hold1 = hq[u + 1].x;

            float r0 = sigf(ar[n].x);
            float r1 = sigf(ar[n].y);
            float z0 = sigf(az[n].x);
            float z1 = sigf(az[n].y);
            float nn0 = htanh(aig[n].x + r0 * ahg[n].x);
            float nn1 = htanh(aig[n].y + r1 * ahg[n].y);
            float hn0 = (1.0f - z0) * nn0 + z0 * hold0;
            float hn1 = (1.0f - z1) * nn1 + z1 * hold1;

            ((float2*)&g_h[(size_t)m * 64])[lane] = make_float2(hn0, hn1);

            float part = hn0 * wo0 + hn1 * wo1;
#pragma unroll
            for (int off = 16; off > 0; off >>= 1)
                part += __shfl_down_sync(0xffffffffu, part, off);
            if (lane == 0) {
                float xn = part + bout;
                g_xn[m] = xn;
                out[((size_t)b * PREDN + t) * NNODE + (nd0 + n)] = xn;
            }
        }
        __syncwarp();
    }

    // restore launch-invariant state on the final step (graph-replay idempotence)
    if (cleanup) {
        int gtid = blockIdx.x * 512 + tid;
        if (gtid < NNODE) g_cnt[gtid] = 0;
        if (gtid < 4) g_dsum[gtid] = 0.0;
    }
}

// ---------------- host launcher ----------------
extern "C" void kernel_launch(void* const* d_in, const int* in_sizes, int n_in,
                              void* d_out, int out_size)
{
    const float* rain    = (const float*)d_in[0];
    const float* feature = (const float*)d_in[1];
    const int*   eidx    = (const int*)d_in[2];
    const float* eattr   = (const float*)d_in[3];
    const float* wmean   = (const float*)d_in[4];
    const float* wstd    = (const float*)d_in[5];
    const float* We1     = (const float*)d_in[6];
    const float* be1     = (const float*)d_in[7];
    const float* We2     = (const float*)d_in[8];
    const float* be2     = (const float*)d_in[9];
    const float* Wn      = (const float*)d_in[10];
    const float* bn      = (const float*)d_in[11];
    const float* Wih     = (const float*)d_in[12];
    const float* bih     = (const float*)d_in[13];
    const float* Whh     = (const float*)d_in[14];
    const float* bhh     = (const float*)d_in[15];
    const float* Wout    = (const float*)d_in[16];
    const float* bout    = (const float*)d_in[17];
    float* out = (float*)d_out;

    cudaFuncSetAttribute(k_gru, cudaFuncAttributeMaxDynamicSharedMemorySize,
                         GRU_SMEM_BYTES);

    // setup: 3 launches; launch #4 = k_edge(t=0) (ncu capture slot)
    k_setup1<<<(NEDGE + 255) / 256, 256>>>(eidx, eattr);
    k_scan<<<1, 1024>>>();
    k_place_pre<<<(NEDGE + 255) / 256, 256>>>(eidx, eattr, We1, be1, rain,
                                              feature, wmean, wstd);

    for (int t = 0; t < PREDN; t++) {
        if (t > 0)
            k_node_pre<<<(BN + 127) / 128, 128>>>(feature, We1, wmean, wstd, t);
        k_edge<<<(BE + 255) / 256, 256>>>(We1, We2, be2, Wn);
        k_gru<<<148, 512, GRU_SMEM_BYTES>>>(bn, Wih, bih, Whh, bhh,
                                            Wout, bout, feature, out, t,
                                            (t == PREDN - 1) ? 1 : 0);
    }
}

// round 16
// speedup vs baseline: 1.5974x; 1.5974x over previous
#include <cuda_runtime.h>
#include <math.h>

// ---------------- problem constants ----------------
#define BB     4
#define HISTN  24
#define PREDN  12
#define NNODE  10000
#define NEDGE  160000
#define TTOT   (HISTN + PREDN)   // 36
#define BN     (BB * NNODE)      // 40000
#define BE     (BB * NEDGE)      // 640000
#define FEATD  31
#define HIDN   64

// ---------------- persistent device scratch ----------------
__device__ __align__(16) float g_ps[(size_t)BN * 32];
__device__ __align__(16) float g_pt[(size_t)BN * 32];
__device__ float g_spd[BN];
__device__ float g_dir[BN];
__device__ __align__(16) float4 g_base4[8][NEDGE];     // transposed base planes
__device__ __align__(16) float g_agg[(size_t)BN * 12]; // 9 used + 3 pad
__device__ __align__(16) float g_h[(size_t)BN * 64];
__device__ float g_xn[BN];
__device__ float g_stats[4];     // mean0, mean1, rstd0, rstd1
__device__ double g_dsum[4];     // s0, s1, q0, q1 (restored to 0 by last k_gru)

// counting-sort state (g_cnt restored to 0 by last k_gru each launch)
__device__ int g_cnt[NNODE];
__device__ int4 g_erec[NEDGE];   // {es, et, dist_bits, cdir_bits} sorted by es

// HW tanh (sm_75+, 1 MUFU op)
__device__ __forceinline__ float htanh(float x) {
    float y;
    asm("tanh.approx.f32 %0, %1;" : "=f"(y) : "f"(x));
    return y;
}
__device__ __forceinline__ float sigf(float x) {
    return fmaf(0.5f, htanh(0.5f * x), 0.5f);
}

// packed fp32x2 FMA (Blackwell)
__device__ __forceinline__ float2 ffma2(float2 a, float2 b, float2 c) {
    float2 d;
    asm("fma.rn.f32x2 %0, %1, %2, %3;"
        : "=l"(*reinterpret_cast<unsigned long long*>(&d))
        : "l"(*reinterpret_cast<const unsigned long long*>(&a)),
          "l"(*reinterpret_cast<const unsigned long long*>(&b)),
          "l"(*reinterpret_cast<const unsigned long long*>(&c)));
    return d;
}

// vector reduction to global (no return) — sm_90+
__device__ __forceinline__ void red4(float* p, float a, float b, float c, float d) {
    asm volatile("red.global.add.v4.f32 [%0], {%1, %2, %3, %4};"
                 :: "l"(p), "f"(a), "f"(b), "f"(c), "f"(d) : "memory");
}

// ---------------- shared node-pre math ----------------
__device__ __forceinline__ void node_pre_math(
    int idx, float xn_v, const float* __restrict__ frow,
    const float* __restrict__ We1s,
    const float* __restrict__ wmean, const float* __restrict__ wstd)
{
    float x[32];
    x[0] = xn_v;
#pragma unroll
    for (int k = 0; k < FEATD; k++) x[1 + k] = frow[k];

    float2 a2[16];
#pragma unroll
    for (int q = 0; q < 16; q++) a2[q] = make_float2(0.f, 0.f);
#pragma unroll
    for (int k = 0; k < 32; k++) {
        float2 xd = make_float2(x[k], x[k]);
        const float4* w = (const float4*)&We1s[k * 32];
#pragma unroll
        for (int q = 0; q < 8; q++) {
            float4 wv = w[q];
            a2[2 * q]     = ffma2(make_float2(wv.x, wv.y), xd, a2[2 * q]);
            a2[2 * q + 1] = ffma2(make_float2(wv.z, wv.w), xd, a2[2 * q + 1]);
        }
    }
    float2* pso = (float2*)&g_ps[(size_t)idx * 32];
#pragma unroll
    for (int q = 0; q < 16; q++) pso[q] = a2[q];

#pragma unroll
    for (int q = 0; q < 16; q++) a2[q] = make_float2(0.f, 0.f);
#pragma unroll
    for (int k = 0; k < 32; k++) {
        float2 xd = make_float2(x[k], x[k]);
        const float4* w = (const float4*)&We1s[(32 + k) * 32];
#pragma unroll
        for (int q = 0; q < 8; q++) {
            float4 wv = w[q];
            a2[2 * q]     = ffma2(make_float2(wv.x, wv.y), xd, a2[2 * q]);
            a2[2 * q + 1] = ffma2(make_float2(wv.z, wv.w), xd, a2[2 * q + 1]);
        }
    }
    float2* pto = (float2*)&g_pt[(size_t)idx * 32];
#pragma unroll
    for (int q = 0; q < 16; q++) pto[q] = a2[q];

    g_spd[idx] = fmaf(x[30], wstd[0], wmean[0]);
    g_dir[idx] = fmaf(x[31], wstd[1], wmean[1]);

    float4 z4 = make_float4(0.f, 0.f, 0.f, 0.f);
    float4* ag = (float4*)&g_agg[(size_t)idx * 12];
    ag[0] = z4; ag[1] = z4; ag[2] = z4;
}

// ---------------- L1 (setup): histogram + stats partials ----------------
__global__ __launch_bounds__(256) void k_setup1(const int* __restrict__ eidx,
                                                const float* __restrict__ eattr) {
    __shared__ double sb[256];
    int tid = threadIdx.x;
    int e = blockIdx.x * 256 + tid;
    double a = 0.0, c = 0.0;
    if (e < NEDGE) {
        atomicAdd(&g_cnt[eidx[e]], 1);
        a = (double)eattr[2 * e];
        c = (double)eattr[2 * e + 1];
    }
    double vals[4] = { a, c, a * a, c * c };
#pragma unroll
    for (int v = 0; v < 4; v++) {
        sb[tid] = vals[v];
        __syncthreads();
        for (int off = 128; off > 0; off >>= 1) {
            if (tid < off) sb[tid] += sb[tid + off];
            __syncthreads();
        }
        if (tid == 0) atomicAdd(&g_dsum[v], sb[0]);
        __syncthreads();
    }
}

// ---------------- L2 (setup): finalize stats + exclusive scan ----------------
__global__ void k_scan() {
    __shared__ int s[1024];
    int tid = threadIdx.x;
    if (tid == 0) {
        double m0 = g_dsum[0] / NEDGE, m1 = g_dsum[1] / NEDGE;
        double v0 = (g_dsum[2] - (double)NEDGE * m0 * m0) / (double)(NEDGE - 1);
        double v1 = (g_dsum[3] - (double)NEDGE * m1 * m1) / (double)(NEDGE - 1);
        g_stats[0] = (float)m0;
        g_stats[1] = (float)m1;
        g_stats[2] = (float)(1.0 / sqrt(v0));
        g_stats[3] = (float)(1.0 / sqrt(v1));
    }
    int sum = 0;
    if (tid < 1000) {
#pragma unroll
        for (int j = 0; j < 10; j++) sum += g_cnt[tid * 10 + j];
    }
    s[tid] = sum;
    __syncthreads();
    for (int off = 1; off < 1024; off <<= 1) {
        int v = (tid >= off) ? s[tid - off] : 0;
        __syncthreads();
        s[tid] += v;
        __syncthreads();
    }
    if (tid < 1000) {
        int run = (tid > 0) ? s[tid - 1] : 0;
#pragma unroll
        for (int j = 0; j < 10; j++) {
            int c = g_cnt[tid * 10 + j];
            g_cnt[tid * 10 + j] = run;
            run += c;
        }
    }
}

// ---------------- L3 (setup): place edges + base planes + state init + node_pre(t=0) ----------------
__global__ __launch_bounds__(256) void k_place_pre(
    const int* __restrict__ eidx,
    const float* __restrict__ eattr,
    const float* __restrict__ We1,
    const float* __restrict__ be1,
    const float* __restrict__ rain,
    const float* __restrict__ feature,
    const float* __restrict__ wmean,
    const float* __restrict__ wstd)
{
    __shared__ __align__(16) float We1s[64 * 32];
    int tid = threadIdx.x;
    for (int i = tid; i < 64 * 32; i += 256) We1s[i] = We1[i];
    __syncthreads();

    int e = blockIdx.x * 256 + tid;

    if (e < BN) {
        int b = e / NNODE;
        int n = e - b * NNODE;
        float xn_v = rain[((size_t)b * HISTN + (HISTN - 1)) * NNODE + n];
        g_xn[e] = xn_v;
        float4 z = make_float4(0.f, 0.f, 0.f, 0.f);
        float4* hp = (float4*)&g_h[(size_t)e * 64];
#pragma unroll
        for (int q = 0; q < 16; q++) hp[q] = z;
        const float* frow = feature + ((size_t)(b * TTOT + HISTN + 0) * NNODE + n) * FEATD;
        node_pre_math(e, xn_v, frow, We1s, wmean, wstd);
    }

    if (e < NEDGE) {
        int es = eidx[e];
        int et = eidx[NEDGE + e];
        int pos = atomicAdd(&g_cnt[es], 1);
        float d = eattr[2 * e];
        float c = eattr[2 * e + 1];
        int4 rec;
        rec.x = es; rec.y = et;
        rec.z = __float_as_int(d);
        rec.w = __float_as_int(c);
        g_erec[pos] = rec;

        float m0 = g_stats[0], m1 = g_stats[1], r0 = g_stats[2], r1 = g_stats[3];
        float ean0 = (d - m0) * r0;
        float ean1 = (c - m1) * r1;
#pragma unroll
        for (int q = 0; q < 8; q++) {
            float4 v;
            v.x = fmaf(ean0, We1[64 * 32 + 4 * q + 0], fmaf(ean1, We1[65 * 32 + 4 * q + 0], be1[4 * q + 0]));
            v.y = fmaf(ean0, We1[64 * 32 + 4 * q + 1], fmaf(ean1, We1[65 * 32 + 4 * q + 1], be1[4 * q + 1]));
            v.z = fmaf(ean0, We1[64 * 32 + 4 * q + 2], fmaf(ean1, We1[65 * 32 + 4 * q + 2], be1[4 * q + 2]));
            v.w = fmaf(ean0, We1[64 * 32 + 4 * q + 3], fmaf(ean1, We1[65 * 32 + 4 * q + 3], be1[4 * q + 3]));
            g_base4[q][pos] = v;
        }
    }
}

// ---------------- per-step: per-node precompute (t >= 1) ----------------
__global__ __launch_bounds__(128) void k_node_pre(
    const float* __restrict__ feature,
    const float* __restrict__ We1,
    const float* __restrict__ wmean,
    const float* __restrict__ wstd,
    int t)
{
    __shared__ __align__(16) float We1s[64 * 32];
    int tid = threadIdx.x;
    for (int i = tid; i < 64 * 32; i += 128) We1s[i] = We1[i];
    __syncthreads();

    int idx = blockIdx.x * 128 + tid;
    if (idx >= BN) return;
    int b = idx / NNODE;
    int n = idx - b * NNODE;
    const float* frow = feature + ((size_t)(b * TTOT + HISTN + t) * NNODE + n) * FEATD;
    node_pre_math(idx, g_xn[idx], frow, We1s, wmean, wstd);
}

// ---------------- per-step: edge MLP + Wn projection + vector scatter-add ----------------
__global__ __launch_bounds__(256, 4) void k_edge(
    const float* __restrict__ We1,
    const float* __restrict__ We2,
    const float* __restrict__ be2,
    const float* __restrict__ Wn)
{
    __shared__ __align__(16) float We2sp[32 * 32];  // row stride 32, cols>=30 zero
    __shared__ __align__(16) float Wn_p[30 * 12];   // row stride 12, cols>=9 zero
    __shared__ __align__(16) float w66s[32];
    __shared__ __align__(16) float be2s[32];
    __shared__ float stage[8][32 * 33];             // per-warp pt tile, pad 33
    int tid = threadIdx.x;
    int wid = tid >> 5;
    int lane = tid & 31;

    for (int i = tid; i < 32 * 32; i += 256) We2sp[i] = 0.f;
    for (int i = tid; i < 30 * 12; i += 256) Wn_p[i] = 0.f;
    if (tid < 32) be2s[tid] = 0.f;
    __syncthreads();
    for (int i = tid; i < 32 * 30; i += 256) We2sp[(i / 30) * 32 + (i % 30)] = We2[i];
    for (int i = tid; i < 30 * 9; i += 256) Wn_p[(i / 9) * 12 + (i % 9)] = Wn[i];
    if (tid < 32) w66s[tid] = We1[66 * 32 + tid];
    if (tid < 30) be2s[tid] = be2[tid];
    __syncthreads();

    int gid = blockIdx.x * 256 + tid;       // BE == 2500*256 exactly, no tail
    int pos = gid >> 2;                     // 4 batches of same edge in same warp
    int b = gid & 3;

    int4 er = g_erec[pos];
    int es = er.x;
    int et = er.y;
    float dist = __int_as_float(er.z);
    float cdir = __int_as_float(er.w);
    int rs = b * NNODE + es;
    int rt = b * NNODE + et;

    // ---- cooperative pt stage: row per edge-slot, coalesced 128B line loads ----
    float* st = stage[wid];
#pragma unroll
    for (int r = 0; r < 32; r++) {
        int rowr = __shfl_sync(0xffffffffu, rt, r);
        st[r * 33 + lane] = g_pt[(size_t)rowr * 32 + lane];
    }
    __syncwarp();
    const float* myrow = st + lane * 33;    // conflict-free (stride 33)

    float spd = g_spd[rs];
    float dr = g_dir[rs];
    float theta = fabsf(cdir - dr);
    float ew = fmaxf(0.f, __fdividef(3.0f * spd * __cosf(theta * 22.5f), dist));

    const float4* p4 = (const float4*)&g_ps[(size_t)rs * 32];
    const float4* w4 = (const float4*)w66s;

    float h[32];
#pragma unroll
    for (int q = 0; q < 8; q++) {
        float4 a = p4[q], d = g_base4[q][pos], w = w4[q];
        h[4 * q + 0] = sigf(a.x + myrow[4 * q + 0] + d.x + ew * w.x);
        h[4 * q + 1] = sigf(a.y + myrow[4 * q + 1] + d.y + ew * w.y);
        h[4 * q + 2] = sigf(a.z + myrow[4 * q + 2] + d.z + ew * w.z);
        h[4 * q + 3] = sigf(a.w + myrow[4 * q + 3] + d.w + ew * w.w);
    }

    float2 a2[16];
#pragma unroll
    for (int q = 0; q < 16; q++) a2[q] = make_float2(be2s[2 * q], be2s[2 * q + 1]);
#pragma unroll 8
    for (int i = 0; i < 32; i++) {
        float2 hd = make_float2(h[i], h[i]);
        const float4* wv = (const float4*)&We2sp[i * 32];
#pragma unroll
        for (int q = 0; q < 8; q++) {
            float4 w = wv[q];
            a2[2 * q]     = ffma2(make_float2(w.x, w.y), hd, a2[2 * q]);
            a2[2 * q + 1] = ffma2(make_float2(w.z, w.w), hd, a2[2 * q + 1]);
        }
    }

    // sigmoid + project to 9 channels via Wn (padded to 12)
    float2 p2[6];
#pragma unroll
    for (int q = 0; q < 6; q++) p2[q] = make_float2(0.f, 0.f);
#pragma unroll
    for (int q = 0; q < 15; q++) {
        float e0 = sigf(a2[q].x);
        float e1 = sigf(a2[q].y);
        float2 e0d = make_float2(e0, e0);
        float2 e1d = make_float2(e1, e1);
        const float4* w0 = (const float4*)&Wn_p[(2 * q) * 12];
        const float4* w1 = (const float4*)&Wn_p[(2 * q + 1) * 12];
#pragma unroll
        for (int r = 0; r < 3; r++) {
            float4 wa = w0[r];
            float4 wb = w1[r];
            p2[2 * r]     = ffma2(make_float2(wa.x, wa.y), e0d, p2[2 * r]);
            p2[2 * r + 1] = ffma2(make_float2(wa.z, wa.w), e0d, p2[2 * r + 1]);
            p2[2 * r]     = ffma2(make_float2(wb.x, wb.y), e1d, p2[2 * r]);
            p2[2 * r + 1] = ffma2(make_float2(wb.z, wb.w), e1d, p2[2 * r + 1]);
        }
    }

    float v0 = p2[0].x, v1 = p2[0].y, v2 = p2[1].x, v3 = p2[1].y;
    float v4 = p2[2].x, v5 = p2[2].y, v6 = p2[3].x, v7 = p2[3].y;
    float v8 = p2[4].x;

    float* at  = &g_agg[(size_t)rt * 12];
    float* as_ = &g_agg[(size_t)rs * 12];
    red4(at, v0, v1, v2, v3);
    red4(at + 4, v4, v5, v6, v7);
    atomicAdd(at + 8, v8);
    red4(as_, -v0, -v1, -v2, -v3);
    red4(as_ + 4, -v4, -v5, -v6, -v7);
    atomicAdd(as_ + 8, -v8);
}

// ---------------- per-step: node GNN head + GRU + readout ----------------
#define GRU_WBUF_OFF 20624
#define GRU_SMEM_FLOATS (GRU_WBUF_OFF + 16 * 8 * 106 * 2)
#define GRU_SMEM_BYTES  (GRU_SMEM_FLOATS * 4)

__global__ __launch_bounds__(512) void k_gru(
    const float* __restrict__ bn_g,
    const float* __restrict__ Wih_g, const float* __restrict__ bih_g,
    const float* __restrict__ Whh_g, const float* __restrict__ bhh_g,
    const float* __restrict__ Wout_g, const float* __restrict__ bout_g,
    const float* __restrict__ feature,
    float* __restrict__ out, int t, int cleanup)
{
    extern __shared__ __align__(16) float sm[];
    float* Wih_s  = sm;
    float* Whh_s  = sm + 7872;
    float* bih_s  = sm + 20160;
    float* bhh_s  = sm + 20352;
    float* bn_s   = sm + 20544;
    float* Wout_s = sm + 20556;

    int tid = threadIdx.x;
    for (int i = tid; i < 7872; i += 512) Wih_s[i] = Wih_g[i];
    for (int i = tid; i < 12288; i += 512) Whh_s[i] = Whh_g[i];
    if (tid < 192) { bih_s[tid] = bih_g[tid]; bhh_s[tid] = bhh_g[tid]; }
    if (tid < 9) bn_s[tid] = bn_g[tid];
    if (tid < 64) Wout_s[tid] = Wout_g[tid];
    __syncthreads();

    int wid = tid >> 5;
    int lane = tid & 31;
    float2* wb = (float2*)(sm + GRU_WBUF_OFF) + wid * (8 * 106);

    float bout = bout_g[0];
    int u = lane * 2;

    int gw = blockIdx.x * 16 + wid;
    int nwarps = gridDim.x * 16;

    for (int g = gw; g < BN / 8; g += nwarps) {
        int base = g * 8;
        int b = base / NNODE;              // groups never straddle batches (8 | 10000)
        int nd0 = base - b * NNODE;
        const float* fbase = feature + ((size_t)(b * TTOT + HISTN + t) * NNODE + nd0) * FEATD;

#pragma unroll
        for (int n = 0; n < 8; n++) {
            int m = base + n;
            float2* xq = wb + n * 106;
            float2* hq = xq + 42;
            if (lane < 9) {
                float v = sigf(g_agg[(size_t)m * 12 + lane] + bn_s[lane]);
                xq[lane] = make_float2(v, v);
            } else if (lane == 9) {
                float xv = g_xn[m];
                xq[9] = make_float2(xv, xv);
            }
            if (lane < 31) {
                float f = fbase[(size_t)n * FEATD + lane];
                xq[10 + lane] = make_float2(f, f);
            }
            float h0 = g_h[(size_t)m * 64 + lane];
            float h1 = g_h[(size_t)m * 64 + 32 + lane];
            hq[lane] = make_float2(h0, h0);
            hq[32 + lane] = make_float2(h1, h1);
        }
        __syncwarp();

        float2 bi_r = *(const float2*)&bih_s[u];
        float2 bi_z = *(const float2*)&bih_s[u + 64];
        float2 bi_g = *(const float2*)&bih_s[u + 128];
        float2 bh_r = *(const float2*)&bhh_s[u];
        float2 bh_z = *(const float2*)&bhh_s[u + 64];
        float2 bh_g = *(const float2*)&bhh_s[u + 128];

        float2 ar[8], az[8], aig[8], ahg[8];
#pragma unroll
        for (int n = 0; n < 8; n++) {
            ar[n] = make_float2(bi_r.x + bh_r.x, bi_r.y + bh_r.y);
            az[n] = make_float2(bi_z.x + bh_z.x, bi_z.y + bh_z.y);
            aig[n] = bi_g;
            ahg[n] = bh_g;
        }

        const float2* row = (const float2*)Wih_s + lane;
#pragma unroll 2
        for (int k = 0; k < 41; k++) {
            float2 wr = row[0];
            float2 wz = row[32];
            float2 wg = row[64];
#pragma unroll
            for (int n = 0; n < 8; n++) {
                float2 xv = wb[n * 106 + k];
                ar[n]  = ffma2(wr, xv, ar[n]);
                az[n]  = ffma2(wz, xv, az[n]);
                aig[n] = ffma2(wg, xv, aig[n]);
            }
            row += 96;
        }

        const float2* rowh = (const float2*)Whh_s + lane;
#pragma unroll 2
        for (int k = 0; k < 64; k++) {
            float2 wr = rowh[0];
            float2 wz = rowh[32];
            float2 wg = rowh[64];
#pragma unroll
            for (int n = 0; n < 8; n++) {
                float2 hv = wb[n * 106 + 42 + k];
                ar[n]  = ffma2(wr, hv, ar[n]);
                az[n]  = ffma2(wz, hv, az[n]);
                ahg[n] = ffma2(wg, hv, ahg[n]);
            }
            rowh += 96;
        }

        float wo0 = Wout_s[u], wo1 = Wout_s[u + 1];

#pragma unroll
        for (int n = 0; n < 8; n++) {
            int m = base + n;
            const float2* hq = wb + n * 106 + 42;
            float hold0 = hq[u].x;
            float hold1 = hq[u + 1].x;

            float r0 = sigf(ar[n].x);
            float r1 = sigf(ar[n].y);
            float z0 = sigf(az[n].x);
            float z1 = sigf(az[n].y);
            float nn0 = htanh(aig[n].x + r0 * ahg[n].x);
            float nn1 = htanh(aig[n].y + r1 * ahg[n].y);
            float hn0 = (1.0f - z0) * nn0 + z0 * hold0;
            float hn1 = (1.0f - z1) * nn1 + z1 * hold1;

            ((float2*)&g_h[(size_t)m * 64])[lane] = make_float2(hn0, hn1);

            float part = hn0 * wo0 + hn1 * wo1;
#pragma unroll
            for (int off = 16; off > 0; off >>= 1)
                part += __shfl_down_sync(0xffffffffu, part, off);
            if (lane == 0) {
                float xn = part + bout;
                g_xn[m] = xn;
                out[((size_t)b * PREDN + t) * NNODE + (nd0 + n)] = xn;
            }
        }
        __syncwarp();
    }

    // restore launch-invariant state on the final step (graph-replay idempotence)
    if (cleanup) {
        int gtid = blockIdx.x * 512 + tid;
        if (gtid < NNODE) g_cnt[gtid] = 0;
        if (gtid < 4) g_dsum[gtid] = 0.0;
    }
}

// ---------------- host launcher ----------------
extern "C" void kernel_launch(void* const* d_in, const int* in_sizes, int n_in,
                              void* d_out, int out_size)
{
    const float* rain    = (const float*)d_in[0];
    const float* feature = (const float*)d_in[1];
    const int*   eidx    = (const int*)d_in[2];
    const float* eattr   = (const float*)d_in[3];
    const float* wmean   = (const float*)d_in[4];
    const float* wstd    = (const float*)d_in[5];
    const float* We1     = (const float*)d_in[6];
    const float* be1     = (const float*)d_in[7];
    const float* We2     = (const float*)d_in[8];
    const float* be2     = (const float*)d_in[9];
    const float* Wn      = (const float*)d_in[10];
    const float* bn      = (const float*)d_in[11];
    const float* Wih     = (const float*)d_in[12];
    const float* bih     = (const float*)d_in[13];
    const float* Whh     = (const float*)d_in[14];
    const float* bhh     = (const float*)d_in[15];
    const float* Wout    = (const float*)d_in[16];
    const float* bout    = (const float*)d_in[17];
    float* out = (float*)d_out;

    cudaFuncSetAttribute(k_gru, cudaFuncAttributeMaxDynamicSharedMemorySize,
                         GRU_SMEM_BYTES);

    // setup: 3 launches; launch #4 = k_edge(t=0) (ncu capture slot)
    k_setup1<<<(NEDGE + 255) / 256, 256>>>(eidx, eattr);
    k_scan<<<1, 1024>>>();
    k_place_pre<<<(NEDGE + 255) / 256, 256>>>(eidx, eattr, We1, be1, rain,
                                              feature, wmean, wstd);

    for (int t = 0; t < PREDN; t++) {
        if (t > 0)
            k_node_pre<<<(BN + 127) / 128, 128>>>(feature, We1, wmean, wstd, t);
        k_edge<<<(BE + 255) / 256, 256>>>(We1, We2, be2, Wn);
        k_gru<<<148, 512, GRU_SMEM_BYTES>>>(bn, Wih, bih, Whh, bhh,
                                            Wout, bout, feature, out, t,
                                            (t == PREDN - 1) ? 1 : 0);
    }
}